// round 4
// baseline (speedup 1.0000x reference)
#include <cuda_runtime.h>
#include <math.h>

#define B_   8
#define S_   4096
#define H_   1024
#define R_   (B_ * H_)
#define CAP  128
// threshold in lg2 domain: ln(x)+g > 3.3  <=>  lg2(x) + g/ln2 > 3.3/ln2
#define TAU_LG2   4.76107544f
#define INV_LN2   1.44269504f

// ---------------- device scratch (zero-initialized at load; select restores) ----------------
__device__ float2 g_buf[R_ * CAP];   // survivor (score, value) per row
__device__ int    g_cnt[R_];         // zeroed at init; k_select resets after use
__device__ float  g_pooled[R_];

__device__ __forceinline__ float neg_inf() { return __int_as_float(0xff800000); }

__device__ __forceinline__ void flt_test(float x, float g, int r) {
    float sc = fmaf(g, INV_LN2, __log2f(x));  // NaN (x<0) / -inf (x==0): never > TAU
    if (sc > TAU_LG2) {
        int p = atomicAdd(&g_cnt[r], 1);
        if (p < CAP) g_buf[r * CAP + p] = make_float2(sc, x);
    }
}

// ---------------- 1: streaming filter, fully 128-bit ----------------
// Block tile: 128 h x 64 s.
// Phase 1: gumbel float4 loads (half-warp per row, 64B segments), stored to
//   smem transposed [s][h] with XOR swizzle on the h-quad: quad' = (h>>2)^(s&31).
// Phase 2: per s, warp spans 128 h: hidden LDG.128 (512B contiguous),
//   gumbel LDS.128 (conflict-free), 4 LDG.128 front-batched per thread.
__global__ __launch_bounds__(256) void k_filter(const float* __restrict__ hidden,
                                                const float* __restrict__ gumbel) {
    __shared__ float4 sg4[64 * 32];          // 32 KB: sg4[s*32 + swizzled h-quad]
    float* sg = (float*)sg4;

    int blk  = blockIdx.x;                   // 0..4095
    int sblk = blk & 63;                     // 64 s-blocks
    int hblk = (blk >> 6) & 7;               // 8 h-blocks
    int b    = blk >> 9;                     // 8 batches
    int s0   = sblk * 64;
    int h0   = hblk * 128;
    int w    = threadIdx.x >> 5;
    int lane = threadIdx.x & 31;

    // ---- phase 1: gumbel [128h x 64s] -> transposed smem ----
    {
        int c  = lane & 15;                  // float4 chunk along s (s = 4c)
        int hr = lane >> 4;                  // row parity within pair
        const float4* gb = (const float4*)(gumbel + ((size_t)(b * H_ + h0)) * S_ + s0);
#pragma unroll
        for (int a = 0; a < 8; ++a) {
            int hl = w * 16 + 2 * a + hr;    // local h: 0..127
            float4 g4 = gb[(size_t)hl * (S_ / 4) + c];
            int hq = hl >> 2, hk = hl & 3;
            int s = 4 * c;
            sg[(s + 0) * 128 + (((hq) ^ ((s + 0) & 31)) << 2) + hk] = g4.x;
            sg[(s + 1) * 128 + (((hq) ^ ((s + 1) & 31)) << 2) + hk] = g4.y;
            sg[(s + 2) * 128 + (((hq) ^ ((s + 2) & 31)) << 2) + hk] = g4.z;
            sg[(s + 3) * 128 + (((hq) ^ ((s + 3) & 31)) << 2) + hk] = g4.w;
        }
    }
    __syncthreads();

    // ---- phase 2: warp w handles s in [w*8, w*8+8), lane = h-quad ----
    const float4* hbase = (const float4*)(hidden + ((size_t)b * S_ + s0) * H_ + h0) + lane;
    int rb = b * H_ + h0 + lane * 4;         // base row for this thread's 4 h

#pragma unroll
    for (int bi = 0; bi < 2; ++bi) {
        float4 xs[4], gs[4];
#pragma unroll
        for (int j = 0; j < 4; ++j) {
            int s = w * 8 + bi * 4 + j;
            xs[j] = hbase[(size_t)s * (H_ / 4)];
        }
#pragma unroll
        for (int j = 0; j < 4; ++j) {
            int s = w * 8 + bi * 4 + j;
            gs[j] = sg4[s * 32 + (lane ^ (s & 31))];
        }
#pragma unroll
        for (int j = 0; j < 4; ++j) {
            flt_test(xs[j].x, gs[j].x, rb + 0);
            flt_test(xs[j].y, gs[j].y, rb + 1);
            flt_test(xs[j].z, gs[j].z, rb + 2);
            flt_test(xs[j].w, gs[j].w, rb + 3);
        }
    }
}

// ---------------- 2: per-row top-8 over survivors (+ inline exact fallback) ----------------
__global__ __launch_bounds__(256) void k_select(const float* __restrict__ hidden,
                                                const float* __restrict__ gumbel) {
    int row  = (blockIdx.x * blockDim.x + threadIdx.x) >> 5;
    int lane = threadIdx.x & 31;
    if (row >= R_) return;

    const float NI = neg_inf();
    int cnt = g_cnt[row];
    if (lane == 0) g_cnt[row] = 0;           // restore for next graph replay

    float sum = 0.f;

    if (cnt >= 8 && cnt <= CAP) {
        float sc0 = NI, sc1 = NI, sc2 = NI, sc3 = NI;
        float v0 = 0.f, v1 = 0.f, v2 = 0.f, v3 = 0.f;
        int base = row * CAP;
        if (lane      < cnt) { float2 c = g_buf[base + lane];      sc0 = c.x; v0 = c.y; }
        if (lane + 32 < cnt) { float2 c = g_buf[base + lane + 32]; sc1 = c.x; v1 = c.y; }
        if (lane + 64 < cnt) { float2 c = g_buf[base + lane + 64]; sc2 = c.x; v2 = c.y; }
        if (lane + 96 < cnt) { float2 c = g_buf[base + lane + 96]; sc3 = c.x; v3 = c.y; }

        for (int round = 0; round < 8; ++round) {
            float bs = sc0, bv = v0; int bi = 0;
            if (sc1 > bs) { bs = sc1; bv = v1; bi = 1; }
            if (sc2 > bs) { bs = sc2; bv = v2; bi = 2; }
            if (sc3 > bs) { bs = sc3; bv = v3; bi = 3; }
            float m = bs;
#pragma unroll
            for (int off = 16; off > 0; off >>= 1)
                m = fmaxf(m, __shfl_xor_sync(0xffffffffu, m, off));
            unsigned ball = __ballot_sync(0xffffffffu, bs == m);
            int src = __ffs(ball) - 1;
            sum += __shfl_sync(0xffffffffu, bv, src);
            if (lane == src) {
                if      (bi == 0) sc0 = NI;
                else if (bi == 1) sc1 = NI;
                else if (bi == 2) sc2 = NI;
                else              sc3 = NI;
            }
        }
    } else {
        // exact fallback (rare; expected never): warp rescans the full row
        int b = row >> 10;
        int h = row & (H_ - 1);
        const float* hp = hidden + (size_t)b * S_ * H_ + h;
        const float* gp = gumbel + (size_t)row * S_;

        float lsc[8], lv[8];
#pragma unroll
        for (int j = 0; j < 8; ++j) { lsc[j] = NI; lv[j] = 0.f; }

        for (int s = lane; s < S_; s += 32) {
            float x = hp[(size_t)s * H_];
            float g = gp[s];
            float sc = (x > 0.f) ? fmaf(g, INV_LN2, __log2f(x)) : NI;
            if (sc > lsc[7]) {
                lsc[7] = sc; lv[7] = x;
#pragma unroll
                for (int j = 7; j > 0; --j) {
                    if (lsc[j] > lsc[j - 1]) {
                        float ts = lsc[j]; lsc[j] = lsc[j - 1]; lsc[j - 1] = ts;
                        float tv = lv[j];  lv[j]  = lv[j - 1];  lv[j - 1]  = tv;
                    }
                }
            }
        }
        int ptr = 0;
        for (int round = 0; round < 8; ++round) {
            float cand = NI, cval = 0.f;
#pragma unroll
            for (int j = 0; j < 8; ++j)
                if (j == ptr) { cand = lsc[j]; cval = lv[j]; }
            float m = cand;
#pragma unroll
            for (int off = 16; off > 0; off >>= 1)
                m = fmaxf(m, __shfl_xor_sync(0xffffffffu, m, off));
            unsigned ball = __ballot_sync(0xffffffffu, (cand == m) && (ptr < 8));
            if (ball == 0u) continue;        // remaining are -inf: contributes 0 (matches ref)
            int src = __ffs(ball) - 1;
            sum += __shfl_sync(0xffffffffu, cval, src);
            if (lane == src) ptr++;
        }
    }

    if (lane == 0) g_pooled[row] = sum;
}

// ---------------- 3: out = tanh(pooled @ W^T + bias) ----------------
__global__ __launch_bounds__(256) void k_gemm(const float* __restrict__ W,
                                              const float* __restrict__ bias,
                                              float* __restrict__ out) {
    int j = blockIdx.x;
    float acc[8];
#pragma unroll
    for (int bb = 0; bb < 8; ++bb) acc[bb] = 0.f;

    for (int h = threadIdx.x; h < H_; h += 256) {
        float wv = W[(size_t)j * H_ + h];
#pragma unroll
        for (int bb = 0; bb < 8; ++bb)
            acc[bb] += g_pooled[bb * H_ + h] * wv;
    }
#pragma unroll
    for (int bb = 0; bb < 8; ++bb)
#pragma unroll
        for (int off = 16; off > 0; off >>= 1)
            acc[bb] += __shfl_xor_sync(0xffffffffu, acc[bb], off);

    __shared__ float tot[8];
    if (threadIdx.x < 8) tot[threadIdx.x] = 0.f;
    __syncthreads();
    if ((threadIdx.x & 31) == 0) {
#pragma unroll
        for (int bb = 0; bb < 8; ++bb) atomicAdd(&tot[bb], acc[bb]);
    }
    __syncthreads();
    if (threadIdx.x < 8)
        out[threadIdx.x * H_ + j] = tanhf(tot[threadIdx.x] + bias[j]);
}

// ---------------- launch ----------------
extern "C" void kernel_launch(void* const* d_in, const int* in_sizes, int n_in,
                              void* d_out, int out_size) {
    const float* hidden = (const float*)d_in[0];
    const float* gumbel = (const float*)d_in[1];
    const float* W      = (const float*)d_in[2];
    const float* bias   = (const float*)d_in[3];
    float*       out    = (float*)d_out;
    (void)in_sizes; (void)n_in; (void)out_size;

    k_filter<<<4096, 256>>>(hidden, gumbel);
    k_select<<<1024, 256>>>(hidden, gumbel);
    k_gemm  <<<1024, 256>>>(W, bias, out);
}

// round 5
// speedup vs baseline: 1.1354x; 1.1354x over previous
#include <cuda_runtime.h>
#include <math.h>

#define B_   8
#define S_   4096
#define H_   1024
#define R_   (B_ * H_)
#define CAP  128
// threshold in lg2 domain: ln(x)+g > 3.3  <=>  lg2(x) + g/ln2 > 3.3/ln2
#define TAU_LG2   4.76107544f
#define INV_LN2   1.44269504f

// ---------------- device scratch (zero-initialized at load; select restores) ----------------
__device__ float2 g_buf[R_ * CAP];   // survivor (score, value) per row
__device__ int    g_cnt[R_];         // zeroed at init; k_select resets after use
__device__ float  g_pooled[R_];

__device__ __forceinline__ float neg_inf() { return __int_as_float(0xff800000); }

__device__ __forceinline__ void flt_test(float x, float g, int r) {
    float sc = fmaf(g, INV_LN2, __log2f(x));  // NaN (x<0) / -inf (x==0): never > TAU
    if (sc > TAU_LG2) {
        int p = atomicAdd(&g_cnt[r], 1);
        if (p < CAP) g_buf[r * CAP + p] = make_float2(sc, x);
    }
}

// ---------------- 1: streaming filter, 128-bit loads, fixed swizzle ----------------
// Block tile: 128 h x 64 s.
// smem layout: sg4[s*32 + (hq ^ (s>>2))], hq = h-quad (h>>2).
//   store (scalar, transpose): bank = ((hq^c)&7)<<2 | hk with c=lane&15 -> 2-way max
//   load  (LDS.128): per s, lanes give lane^(s>>2) = permutation -> conflict-free
__global__ __launch_bounds__(256) void k_filter(const float* __restrict__ hidden,
                                                const float* __restrict__ gumbel) {
    __shared__ float4 sg4[64 * 32];          // 32 KB
    float* sg = (float*)sg4;

    int blk  = blockIdx.x;                   // 0..4095
    int sblk = blk & 63;                     // 64 s-blocks
    int hblk = (blk >> 6) & 7;               // 8 h-blocks
    int b    = blk >> 9;                     // 8 batches
    int s0   = sblk * 64;
    int h0   = hblk * 128;
    int w    = threadIdx.x >> 5;
    int lane = threadIdx.x & 31;

    // ---- phase 1: gumbel [128h x 64s] -> smem transposed ----
    {
        int c  = lane & 15;                  // float4 chunk along s (s = 4c..4c+3)
        int hr = lane >> 4;
        const float4* gb = (const float4*)(gumbel + ((size_t)(b * H_ + h0)) * S_ + s0);
#pragma unroll
        for (int a = 0; a < 8; ++a) {
            int hl = w * 16 + 2 * a + hr;    // local h: 0..127
            float4 g4 = __ldcs(&gb[(size_t)hl * (S_ / 4) + c]);
            int hq = hl >> 2, hk = hl & 3;
            int sw = (hq ^ c) << 2;          // swizzled quad base (s>>2 == c for all 4)
            sg[(4 * c + 0) * 128 + sw + hk] = g4.x;
            sg[(4 * c + 1) * 128 + sw + hk] = g4.y;
            sg[(4 * c + 2) * 128 + sw + hk] = g4.z;
            sg[(4 * c + 3) * 128 + sw + hk] = g4.w;
        }
    }
    __syncthreads();

    // ---- phase 2: warp w handles s in [w*8, w*8+8), lane = h-quad ----
    const float4* hbase = (const float4*)(hidden + ((size_t)b * S_ + s0 + w * 8) * H_ + h0) + lane;
    int rb = b * H_ + h0 + lane * 4;

    float4 xs[8];
#pragma unroll
    for (int j = 0; j < 8; ++j)
        xs[j] = __ldcs(&hbase[(size_t)j * (H_ / 4)]);

#pragma unroll
    for (int j = 0; j < 8; ++j) {
        int s = w * 8 + j;
        float4 g4 = sg4[s * 32 + (lane ^ (s >> 2))];
        flt_test(xs[j].x, g4.x, rb + 0);
        flt_test(xs[j].y, g4.y, rb + 1);
        flt_test(xs[j].z, g4.z, rb + 2);
        flt_test(xs[j].w, g4.w, rb + 3);
    }
}

// ---------------- 2: per-row top-8 over survivors (+ inline exact fallback) ----------------
__global__ __launch_bounds__(256) void k_select(const float* __restrict__ hidden,
                                                const float* __restrict__ gumbel) {
    int row  = (blockIdx.x * blockDim.x + threadIdx.x) >> 5;
    int lane = threadIdx.x & 31;
    if (row >= R_) return;

    const float NI = neg_inf();
    int cnt = g_cnt[row];
    if (lane == 0) g_cnt[row] = 0;           // restore for next graph replay

    float sum = 0.f;

    if (cnt >= 8 && cnt <= CAP) {
        float sc0 = NI, sc1 = NI, sc2 = NI, sc3 = NI;
        float v0 = 0.f, v1 = 0.f, v2 = 0.f, v3 = 0.f;
        int base = row * CAP;
        if (lane      < cnt) { float2 c = g_buf[base + lane];      sc0 = c.x; v0 = c.y; }
        if (lane + 32 < cnt) { float2 c = g_buf[base + lane + 32]; sc1 = c.x; v1 = c.y; }
        if (lane + 64 < cnt) { float2 c = g_buf[base + lane + 64]; sc2 = c.x; v2 = c.y; }
        if (lane + 96 < cnt) { float2 c = g_buf[base + lane + 96]; sc3 = c.x; v3 = c.y; }

        for (int round = 0; round < 8; ++round) {
            float bs = sc0, bv = v0; int bi = 0;
            if (sc1 > bs) { bs = sc1; bv = v1; bi = 1; }
            if (sc2 > bs) { bs = sc2; bv = v2; bi = 2; }
            if (sc3 > bs) { bs = sc3; bv = v3; bi = 3; }
            float m = bs;
#pragma unroll
            for (int off = 16; off > 0; off >>= 1)
                m = fmaxf(m, __shfl_xor_sync(0xffffffffu, m, off));
            unsigned ball = __ballot_sync(0xffffffffu, bs == m);
            int src = __ffs(ball) - 1;
            sum += __shfl_sync(0xffffffffu, bv, src);
            if (lane == src) {
                if      (bi == 0) sc0 = NI;
                else if (bi == 1) sc1 = NI;
                else if (bi == 2) sc2 = NI;
                else              sc3 = NI;
            }
        }
    } else {
        // exact fallback (rare; expected never): warp rescans the full row
        int b = row >> 10;
        int h = row & (H_ - 1);
        const float* hp = hidden + (size_t)b * S_ * H_ + h;
        const float* gp = gumbel + (size_t)row * S_;

        float lsc[8], lv[8];
#pragma unroll
        for (int j = 0; j < 8; ++j) { lsc[j] = NI; lv[j] = 0.f; }

        for (int s = lane; s < S_; s += 32) {
            float x = hp[(size_t)s * H_];
            float g = gp[s];
            float sc = (x > 0.f) ? fmaf(g, INV_LN2, __log2f(x)) : NI;
            if (sc > lsc[7]) {
                lsc[7] = sc; lv[7] = x;
#pragma unroll
                for (int j = 7; j > 0; --j) {
                    if (lsc[j] > lsc[j - 1]) {
                        float ts = lsc[j]; lsc[j] = lsc[j - 1]; lsc[j - 1] = ts;
                        float tv = lv[j];  lv[j]  = lv[j - 1];  lv[j - 1]  = tv;
                    }
                }
            }
        }
        int ptr = 0;
        for (int round = 0; round < 8; ++round) {
            float cand = NI, cval = 0.f;
#pragma unroll
            for (int j = 0; j < 8; ++j)
                if (j == ptr) { cand = lsc[j]; cval = lv[j]; }
            float m = cand;
#pragma unroll
            for (int off = 16; off > 0; off >>= 1)
                m = fmaxf(m, __shfl_xor_sync(0xffffffffu, m, off));
            unsigned ball = __ballot_sync(0xffffffffu, (cand == m) && (ptr < 8));
            if (ball == 0u) continue;        // remaining are -inf: contributes 0 (matches ref)
            int src = __ffs(ball) - 1;
            sum += __shfl_sync(0xffffffffu, cval, src);
            if (lane == src) ptr++;
        }
    }

    if (lane == 0) g_pooled[row] = sum;
}

// ---------------- 3: out = tanh(pooled @ W^T + bias) ----------------
__global__ __launch_bounds__(256) void k_gemm(const float* __restrict__ W,
                                              const float* __restrict__ bias,
                                              float* __restrict__ out) {
    int j = blockIdx.x;
    float acc[8];
#pragma unroll
    for (int bb = 0; bb < 8; ++bb) acc[bb] = 0.f;

    for (int h = threadIdx.x; h < H_; h += 256) {
        float wv = W[(size_t)j * H_ + h];
#pragma unroll
        for (int bb = 0; bb < 8; ++bb)
            acc[bb] += g_pooled[bb * H_ + h] * wv;
    }
#pragma unroll
    for (int bb = 0; bb < 8; ++bb)
#pragma unroll
        for (int off = 16; off > 0; off >>= 1)
            acc[bb] += __shfl_xor_sync(0xffffffffu, acc[bb], off);

    __shared__ float tot[8];
    if (threadIdx.x < 8) tot[threadIdx.x] = 0.f;
    __syncthreads();
    if ((threadIdx.x & 31) == 0) {
#pragma unroll
        for (int bb = 0; bb < 8; ++bb) atomicAdd(&tot[bb], acc[bb]);
    }
    __syncthreads();
    if (threadIdx.x < 8)
        out[threadIdx.x * H_ + j] = tanhf(tot[threadIdx.x] + bias[j]);
}

// ---------------- launch ----------------
extern "C" void kernel_launch(void* const* d_in, const int* in_sizes, int n_in,
                              void* d_out, int out_size) {
    const float* hidden = (const float*)d_in[0];
    const float* gumbel = (const float*)d_in[1];
    const float* W      = (const float*)d_in[2];
    const float* bias   = (const float*)d_in[3];
    float*       out    = (float*)d_out;
    (void)in_sizes; (void)n_in; (void)out_size;

    k_filter<<<4096, 256>>>(hidden, gumbel);
    k_select<<<1024, 256>>>(hidden, gumbel);
    k_gemm  <<<1024, 256>>>(W, bias, out);
}